// round 16
// baseline (speedup 1.0000x reference)
#include <cuda_runtime.h>
#include <cuda_bf16.h>
#include <cuda_fp16.h>
#include <cstdint>
#include <math.h>

// Problem constants
#define B_  2
#define C1_ 256
#define C2_ 256
#define K2_ 9
#define H_  64
#define W_  64
#define HW_ 4096

// ---------------------------------------------------------------------------
// Scratch (allocation-free: __device__ globals; zero-init covers pad cols)
// ---------------------------------------------------------------------------
// Main weights fp16: [step(18)=tap*2+half][o(256)][136]
__device__ __align__(128) __half g_wA[18 * 256 * 136];
// Conv weights fp16: [step(18)=kk*2+half][ocpad(32)][136]
__device__ __align__(128) __half g_wC[18 * 32 * 136];
// Packed input fp16 channel-quads: [b][c4(64)][hw] as uint2 (4 ch per elem)
__device__ __align__(128) uint2 g_xq[B_ * 64 * HW_];

// ---------------------------------------------------------------------------
// PTX helpers (plain sm_103-legal)
// ---------------------------------------------------------------------------
__device__ __forceinline__ uint32_t smem_u32(const void* p) {
    uint32_t a;
    asm("{ .reg .u64 t; cvta.to.shared.u64 t, %1; cvt.u32.u64 %0, t; }"
        : "=r"(a) : "l"(p));
    return a;
}
__device__ __forceinline__ void cp_async16(uint32_t saddr, const void* gaddr) {
    asm volatile("cp.async.cg.shared.global [%0], [%1], 16;"
                 :: "r"(saddr), "l"(gaddr) : "memory");
}
__device__ __forceinline__ void cp_commit() {
    asm volatile("cp.async.commit_group;" ::: "memory");
}
__device__ __forceinline__ void cp_wait1() {
    asm volatile("cp.async.wait_group 1;" ::: "memory");
}
__device__ __forceinline__ void cp_wait0() {
    asm volatile("cp.async.wait_group 0;" ::: "memory");
}
__device__ __forceinline__ void bar_sync(int id, int cnt) {
    asm volatile("bar.sync %0, %1;" :: "r"(id), "r"(cnt) : "memory");
}
__device__ __forceinline__ void bar_arrive(int id, int cnt) {
    asm volatile("bar.arrive %0, %1;" :: "r"(id), "r"(cnt) : "memory");
}
__device__ __forceinline__ void ldmatrix_x4(uint32_t& r0, uint32_t& r1,
                                            uint32_t& r2, uint32_t& r3,
                                            uint32_t addr) {
    asm volatile("ldmatrix.sync.aligned.m8n8.x4.shared.b16 {%0,%1,%2,%3}, [%4];"
                 : "=r"(r0), "=r"(r1), "=r"(r2), "=r"(r3) : "r"(addr));
}
__device__ __forceinline__ void mma_f16(float& d0, float& d1, float& d2, float& d3,
                                        uint32_t a0, uint32_t a1, uint32_t a2, uint32_t a3,
                                        uint32_t b0, uint32_t b1) {
    asm volatile(
        "mma.sync.aligned.m16n8k16.row.col.f32.f16.f16.f32 "
        "{%0,%1,%2,%3}, {%4,%5,%6,%7}, {%8,%9}, {%0,%1,%2,%3};"
        : "+f"(d0), "+f"(d1), "+f"(d2), "+f"(d3)
        : "r"(a0), "r"(a1), "r"(a2), "r"(a3), "r"(b0), "r"(b1));
}

// Barrier ids (0..15)
#define BAR_CONS  0     // consumers-only sync (256)
#define BAR_META  1     // producers-only meta handoff (256)
#define BAR_OM    2     // om handoff: consumers arrive, producers sync (512)
#define BAR_XT    3     // xtile ready: producers arrive, consumers sync (512)
#define BAR_FULL  4     // +0..3 : B buffer full (512)
#define BAR_EMPTY 8     // +0..3 : B buffer empty (512)
#define BAR_WR    12    // +0,1 : conv weight slot ready (256)
#define BAR_WF    14    // +0,1 : conv weight slot free (256)

// ---------------------------------------------------------------------------
// Kernel 0: pack everything (weights fp16 + x channel-quads)
// ---------------------------------------------------------------------------
__global__ void pack_all(const float* __restrict__ w_dcn,
                         const float* __restrict__ w_off,
                         const float* __restrict__ x) {
    int idx = blockIdx.x * 256 + threadIdx.x;
    if (idx < 9 * 256 * 256) {
        int t = idx >> 16;
        int r = idx & 65535;
        int o = r >> 8;
        int c = r & 255;
        float w = w_dcn[o * (C1_ * K2_) + c * K2_ + t];
        int s = t * 2 + (c >> 7);
        int cl = c & 127;
        g_wA[(size_t)s * (256 * 136) + (size_t)o * 136 + cl] = __float2half_rn(w);
    }
    if (idx < 27 * 2304) {
        int oc = idx / 2304;
        int r  = idx % 2304;
        int c  = r / 9;
        int kk = r % 9;
        int s = kk * 2 + (c >> 7);
        int cl = c & 127;
        g_wC[(size_t)s * (32 * 136) + (size_t)oc * 136 + cl] =
            __float2half_rn(w_off[idx]);
    }
    if (idx < B_ * 64 * HW_) {
        int s  = idx & (HW_ - 1);
        int r  = idx >> 12;
        int c4 = r & 63;
        int b  = r >> 6;
        const float* xp = x + ((size_t)(b * C1_ + c4 * 4) << 12) + s;
        __half2 lo = __floats2half2_rn(xp[0],       xp[HW_]);
        __half2 hi = __floats2half2_rn(xp[2 * HW_], xp[3 * HW_]);
        uint2 v;
        v.x = *(uint32_t*)&lo;
        v.y = *(uint32_t*)&hi;
        g_xq[idx] = v;
    }
}

// ---------------------------------------------------------------------------
// Fused kernel, 512 threads: warps 0-7 consumers, 8-15 producers.
// Phase 1: implicit-im2col conv GEMM from resident xtile -> om smem.
// Phase 2: DCN GEMM (4-deep B pipeline, per-warp A double buffers) + BN+SiLU.
// ---------------------------------------------------------------------------
#define WROW      136
#define WROWB     272
#define WSLICE_B  8704u
#define WWARP_B   17408u
#define BBASE     139264u              // 8 * WWARP_B ; B bufs: 4 x 17408
#define BBUF_B    17408u
#define META_O    208896u              // BBASE + 4*17408
#define SMEM_BYTES (META_O + 2048u + 8192u)   // 219136
// xtile: [y(3)][ci(66)][c(264 halves)] at smem offset 0
#define XT_CI_B   528u
#define XT_Y_B    34848u

__global__ __launch_bounds__(512, 1) void dcn_fused(const float* __restrict__ b_off,
                                                    const float* __restrict__ gamma,
                                                    const float* __restrict__ beta,
                                                    const float* __restrict__ rmean,
                                                    const float* __restrict__ rvar,
                                                    float* __restrict__ out) {
    extern __shared__ __align__(128) unsigned char smem_raw[];
    const uint32_t smem_base = smem_u32(smem_raw);

    int b = blockIdx.x >> 6;
    int h = blockIdx.x & 63;
    int tid = threadIdx.x;
    int wid = tid >> 5;
    int lane = tid & 31;

    float* swt  = (float*)(smem_raw + META_O);
    int*   sidx = (int*)(smem_raw + META_O + 1024);
    float* om   = (float*)(smem_raw + META_O + 2048);   // [oc][64]
    const uint2* xqb = g_xq + ((size_t)b << 18);

    if (wid >= 8) {
        // ========================= PRODUCERS (8 warps) =========================
        int ptid = tid - 256;
        int p  = ptid & 63;
        int cg = ptid >> 6;

        // ---- phase 1: fill xtile once (3 rows, 66 cols incl. zero borders)
        for (int idx = ptid; idx < 3 * 66 * 8; idx += 256) {
            int g8 = idx & 7;
            int rr = idx >> 3;
            int ci = rr % 66;
            int y  = rr / 66;
            int gy = h - 1 + y;
            int col = ci - 1;
            unsigned char* dstp = smem_raw + (uint32_t)y * XT_Y_B +
                                  (uint32_t)ci * XT_CI_B + (uint32_t)g8 * 64u;
            if (gy >= 0 && gy < H_ && col >= 0 && col < W_) {
                int si = gy * W_ + col;
                uint2 v[8];
#pragma unroll
                for (int j = 0; j < 8; ++j)
                    v[j] = xqb[((size_t)(g8 * 8 + j) << 12) + si];
#pragma unroll
                for (int j = 0; j < 8; ++j)
                    *(uint2*)(dstp + j * 8) = v[j];
            } else {
                uint4 z = make_uint4(0u, 0u, 0u, 0u);
#pragma unroll
                for (int j = 0; j < 4; ++j)
                    *(uint4*)(dstp + j * 16) = z;
            }
        }
        bar_arrive(BAR_XT, 512);

        // wait for consumers to publish om
        bar_sync(BAR_OM, 512);

        auto make_meta = [&](int t) {
            bar_sync(BAR_META, 256);
            if (ptid < 64) {
                int w = ptid;
                float py = (float)(h - 1 + t / 3) + om[(2 * t) * 64 + w];
                float px = (float)(w - 1 + t % 3) + om[(2 * t + 1) * 64 + w];
                float m = 1.f / (1.f + __expf(-om[(18 + t) * 64 + w]));
                float y0f = floorf(py), x0f = floorf(px);
                float ly = py - y0f, lx = px - x0f;
                int y0 = (int)y0f, x0 = (int)x0f;
                int y1 = y0 + 1, x1 = x0 + 1;
                float vy0 = (y0 >= 0 && y0 < H_) ? 1.f : 0.f;
                float vy1 = (y1 >= 0 && y1 < H_) ? 1.f : 0.f;
                float vx0 = (x0 >= 0 && x0 < W_) ? 1.f : 0.f;
                float vx1 = (x1 >= 0 && x1 < W_) ? 1.f : 0.f;
                int cy0 = min(max(y0, 0), H_ - 1), cy1 = min(max(y1, 0), H_ - 1);
                int cx0 = min(max(x0, 0), W_ - 1), cx1 = min(max(x1, 0), W_ - 1);
                swt[0 * 64 + w] = (1.f - ly) * (1.f - lx) * m * vy0 * vx0;
                swt[1 * 64 + w] = (1.f - ly) * lx * m * vy0 * vx1;
                swt[2 * 64 + w] = ly * (1.f - lx) * m * vy1 * vx0;
                swt[3 * 64 + w] = ly * lx * m * vy1 * vx1;
                sidx[0 * 64 + w] = cy0 * W_ + cx0;
                sidx[1 * 64 + w] = cy0 * W_ + cx1;
                sidx[2 * 64 + w] = cy1 * W_ + cx0;
                sidx[3 * 64 + w] = cy1 * W_ + cx1;
            }
            bar_sync(BAR_META, 256);
        };

        auto make_chunk = [&](int s) {
            int q = s & 1;
            int i0 = sidx[p],       i1 = sidx[64 + p];
            int i2 = sidx[128 + p], i3 = sidx[192 + p];
            float w0 = swt[p],       w1 = swt[64 + p];
            float w2 = swt[128 + p], w3 = swt[192 + p];
            unsigned char* Bb = smem_raw + BBASE + (uint32_t)(s & 3) * BBUF_B;
            uint32_t rowoff = (uint32_t)p * WROWB;
#pragma unroll
            for (int g2 = 0; g2 < 2; ++g2) {
                uint2 t[4][4];
#pragma unroll
                for (int j = 0; j < 4; ++j) {
                    int c4 = q * 32 + cg * 8 + g2 * 4 + j;
                    const uint2* base = xqb + ((size_t)c4 << 12);
                    t[j][0] = base[i0]; t[j][1] = base[i1];
                    t[j][2] = base[i2]; t[j][3] = base[i3];
                }
#pragma unroll
                for (int j = 0; j < 4; ++j) {
                    float2 a0 = __half22float2(*(__half2*)&t[j][0].x);
                    float2 b0 = __half22float2(*(__half2*)&t[j][1].x);
                    float2 c0 = __half22float2(*(__half2*)&t[j][2].x);
                    float2 d0 = __half22float2(*(__half2*)&t[j][3].x);
                    float2 a1 = __half22float2(*(__half2*)&t[j][0].y);
                    float2 b1 = __half22float2(*(__half2*)&t[j][1].y);
                    float2 c1 = __half22float2(*(__half2*)&t[j][2].y);
                    float2 d1 = __half22float2(*(__half2*)&t[j][3].y);
                    float2 rlo, rhi;
                    rlo.x = a0.x * w0 + b0.x * w1 + c0.x * w2 + d0.x * w3;
                    rlo.y = a0.y * w0 + b0.y * w1 + c0.y * w2 + d0.y * w3;
                    rhi.x = a1.x * w0 + b1.x * w1 + c1.x * w2 + d1.x * w3;
                    rhi.y = a1.y * w0 + b1.y * w1 + c1.y * w2 + d1.y * w3;
                    __half2 hlo = __floats2half2_rn(rlo.x, rlo.y);
                    __half2 hhi = __floats2half2_rn(rhi.x, rhi.y);
                    uint2 v;
                    v.x = *(uint32_t*)&hlo;
                    v.y = *(uint32_t*)&hhi;
                    *(uint2*)(Bb + rowoff +
                              (uint32_t)(cg * 8 + g2 * 4 + j) * 8u) = v;
                }
            }
        };

        // ---- phase 2: 4-deep pipeline (skip empty-wait for first 4 steps)
        for (int s = 0; s < 18; ++s) {
            if ((s & 1) == 0) make_meta(s >> 1);
            if (s >= 4) bar_sync(BAR_EMPTY + (s & 3), 512);
            make_chunk(s);
            bar_arrive(BAR_FULL + (s & 3), 512);
        }
    } else {
        // ========================= CONSUMERS (8 warps) =========================
        int a_row = lane & 15;
        int a_cad = (lane >= 16) ? 8 : 0;
        int b_row = (lane & 7) + ((lane >= 16) ? 8 : 0);
        int b_cad = ((lane >> 3) & 1) * 8;
        int g4 = lane >> 2;
        int t4 = lane & 3;

        uint32_t wdst0 = smem_base + (uint32_t)wid * WWARP_B;

        // ---- phase 1: implicit-im2col conv MMA (9 taps from xtile)
        {
            int rgn  = wid >> 1;
            int half = wid & 1;

            float accC[2][4];
#pragma unroll
            for (int mt = 0; mt < 2; mt++)
#pragma unroll
                for (int j = 0; j < 4; j++) accC[mt][j] = 0.f;

            const uint32_t slot_base = smem_base + BBASE;

            // warp 0 pre-stages conv weight taps 0 and 1 into the two slots
            if (wid == 0) {
#pragma unroll
                for (int t0 = 0; t0 < 2; ++t0) {
                    const unsigned char* src =
                        (const unsigned char*)g_wC + (size_t)t0 * 17408u;
                    uint32_t dst = slot_base + (uint32_t)t0 * 17408u;
#pragma unroll
                    for (int j = 0; j < 34; ++j) {       // 34*32*16B = 17408B
                        uint32_t off = (uint32_t)(lane + j * 32) * 16u;
                        cp_async16(dst + off, src + off);
                    }
                    cp_commit();
                }
                cp_wait1();                              // tap0 complete
                bar_arrive(BAR_WR + 0, 256);
            }

            bar_sync(BAR_XT, 512);                       // xtile ready

            for (int t = 0; t < 9; ++t) {
                int slot = t & 1;
                if (wid != 0) bar_sync(BAR_WR + slot, 256);
                uint32_t wslot = slot_base + (uint32_t)slot * 17408u;
                int ky = t / 3, kx = t % 3;
                int ci = rgn * 16 + b_row + kx;
                uint32_t brow = smem_base + (uint32_t)ky * XT_Y_B +
                                (uint32_t)ci * XT_CI_B;

#pragma unroll
                for (int chunk = 0; chunk < 2; ++chunk) {
#pragma unroll
                    for (int ks = 0; ks < 8; ++ks) {
                        uint32_t addrB = brow +
                            (uint32_t)(chunk * 128 + ks * 16 + b_cad) * 2;
                        uint32_t B0, B1, B2, B3;
                        ldmatrix_x4(B0, B1, B2, B3, addrB);
                        uint32_t b0 = half ? B2 : B0, b1 = half ? B3 : B1;
#pragma unroll
                        for (int mt = 0; mt < 2; ++mt) {
                            uint32_t aaddr = wslot + (uint32_t)chunk * 8704u +
                                (uint32_t)((mt * 16 + a_row) * WROW +
                                           ks * 16 + a_cad) * 2;
                            uint32_t A0, A1, A2, A3;
                            ldmatrix_x4(A0, A1, A2, A3, aaddr);
                            float* d = accC[mt];
                            mma_f16(d[0], d[1], d[2], d[3], A0, A1, A2, A3, b0, b1);
                        }
                    }
                }

                if (wid == 0) {
                    if (t + 2 <= 8) {
                        bar_sync(BAR_WF + slot, 256);    // slot free
                        const unsigned char* src =
                            (const unsigned char*)g_wC + (size_t)(t + 2) * 17408u;
                        uint32_t dst = slot_base + (uint32_t)slot * 17408u;
#pragma unroll
                        for (int j = 0; j < 34; ++j) {
                            uint32_t off = (uint32_t)(lane + j * 32) * 16u;
                            cp_async16(dst + off, src + off);
                        }
                        cp_commit();
                    }
                    if (t + 1 <= 8) {
                        if (t + 2 <= 8) cp_wait1(); else cp_wait0();
                        bar_arrive(BAR_WR + ((t + 1) & 1), 256);
                    }
                } else {
                    if (t + 2 <= 8) bar_arrive(BAR_WF + slot, 256);
                }
            }

            // conv epilogue -> om smem (+ bias)
            int col0 = rgn * 16 + half * 8;
#pragma unroll
            for (int mt = 0; mt < 2; ++mt) {
                int oc_lo = mt * 16 + g4;
                int oc_hi = oc_lo + 8;
                int col = col0 + t4 * 2;
                if (oc_lo < 27) {
                    float bo = b_off[oc_lo];
                    om[oc_lo * 64 + col]     = accC[mt][0] + bo;
                    om[oc_lo * 64 + col + 1] = accC[mt][1] + bo;
                }
                if (oc_hi < 27) {
                    float bo = b_off[oc_hi];
                    om[oc_hi * 64 + col]     = accC[mt][2] + bo;
                    om[oc_hi * 64 + col + 1] = accC[mt][3] + bo;
                }
            }
            bar_arrive(BAR_OM, 512);     // om published
            bar_sync(BAR_CONS, 256);     // all consumers done reading xtile/slots
        }

        // ---- phase 2: main DCN MMA (fp16; warp owns o in [32w, 32w+32))
        int o0 = wid * 32;
        float acc[2][8][4];
#pragma unroll
        for (int mt = 0; mt < 2; mt++)
#pragma unroll
            for (int nt = 0; nt < 8; nt++)
#pragma unroll
                for (int j = 0; j < 4; j++) acc[mt][nt][j] = 0.f;

        const unsigned char* wsrc0 = (const unsigned char*)g_wA +
                                     (size_t)wid * 8704u;

        auto cpW = [&](int s) {
            const unsigned char* src = wsrc0 + (size_t)s * 69632u;
            uint32_t dst = wdst0 + (uint32_t)(s & 1) * WSLICE_B;
#pragma unroll
            for (int j = 0; j < 17; ++j) {
                uint32_t off = (uint32_t)(lane + j * 32) * 16u;
                cp_async16(dst + off, src + off);
            }
            cp_commit();
        };

        cpW(0);

        for (int s = 0; s < 18; ++s) {
            if (s < 17) { cpW(s + 1); cp_wait1(); }
            else        { cp_wait0(); }
            bar_sync(BAR_FULL + (s & 3), 512);

            uint32_t wreg = wdst0 + (uint32_t)(s & 1) * WSLICE_B;
            uint32_t breg = smem_base + BBASE + (uint32_t)(s & 3) * BBUF_B;

#pragma unroll
            for (int ks = 0; ks < 8; ++ks) {
                uint32_t A[2][4];
#pragma unroll
                for (int mt = 0; mt < 2; ++mt) {
                    uint32_t aaddr = wreg +
                        (uint32_t)((mt * 16 + a_row) * WROW + ks * 16 + a_cad) * 2;
                    ldmatrix_x4(A[mt][0], A[mt][1], A[mt][2], A[mt][3], aaddr);
                }
                uint32_t Bf[16];
#pragma unroll
                for (int pr = 0; pr < 4; ++pr) {
                    uint32_t addr = breg +
                        (uint32_t)((pr * 16 + b_row) * WROW + ks * 16 + b_cad) * 2;
                    ldmatrix_x4(Bf[pr * 4 + 0], Bf[pr * 4 + 1],
                                Bf[pr * 4 + 2], Bf[pr * 4 + 3], addr);
                }
#pragma unroll
                for (int mt = 0; mt < 2; ++mt) {
#pragma unroll
                    for (int nt = 0; nt < 8; ++nt) {
                        float* d = acc[mt][nt];
                        mma_f16(d[0], d[1], d[2], d[3],
                                A[mt][0], A[mt][1], A[mt][2], A[mt][3],
                                Bf[nt * 2], Bf[nt * 2 + 1]);
                    }
                }
            }
            bar_arrive(BAR_EMPTY + (s & 3), 512);
        }

        // ---- epilogue: BN + SiLU
#pragma unroll
        for (int mt = 0; mt < 2; ++mt) {
            int o_lo = o0 + mt * 16 + g4;
            int o_hi = o_lo + 8;
            float invl = gamma[o_lo] * rsqrtf(rvar[o_lo] + 1e-5f);
            float bbl  = beta[o_lo] - rmean[o_lo] * invl;
            float invh = gamma[o_hi] * rsqrtf(rvar[o_hi] + 1e-5f);
            float bbh  = beta[o_hi] - rmean[o_hi] * invh;
            float* opl = out + (((size_t)b * C2_ + o_lo) * H_ + h) * W_;
            float* oph = out + (((size_t)b * C2_ + o_hi) * H_ + h) * W_;
#pragma unroll
            for (int nt = 0; nt < 8; ++nt) {
                int pp = nt * 8 + t4 * 2;
                float y0v = acc[mt][nt][0] * invl + bbl;
                float y1v = acc[mt][nt][1] * invl + bbl;
                float y2v = acc[mt][nt][2] * invh + bbh;
                float y3v = acc[mt][nt][3] * invh + bbh;
                float2 vlo, vhi;
                vlo.x = y0v / (1.f + __expf(-y0v));
                vlo.y = y1v / (1.f + __expf(-y1v));
                vhi.x = y2v / (1.f + __expf(-y2v));
                vhi.y = y3v / (1.f + __expf(-y3v));
                *(float2*)(opl + pp) = vlo;
                *(float2*)(oph + pp) = vhi;
            }
        }
    }
}

// ---------------------------------------------------------------------------
extern "C" void kernel_launch(void* const* d_in, const int* in_sizes, int n_in,
                              void* d_out, int out_size) {
    const float* x      = (const float*)d_in[0];
    const float* w_off  = (const float*)d_in[1];
    const float* b_off  = (const float*)d_in[2];
    const float* w_dcn  = (const float*)d_in[3];
    const float* gamma  = (const float*)d_in[4];
    const float* beta   = (const float*)d_in[5];
    const float* rmean  = (const float*)d_in[6];
    const float* rvar   = (const float*)d_in[7];
    float* out = (float*)d_out;

    cudaFuncSetAttribute(dcn_fused, cudaFuncAttributeMaxDynamicSharedMemorySize,
                         SMEM_BYTES);

    pack_all<<<2304, 256>>>(w_dcn, w_off, x);
    dcn_fused<<<B_ * H_, 512, SMEM_BYTES>>>(b_off, gamma, beta, rmean, rvar, out);
}

// round 17
// speedup vs baseline: 1.0702x; 1.0702x over previous
#include <cuda_runtime.h>
#include <cuda_bf16.h>
#include <cuda_fp16.h>
#include <cstdint>
#include <math.h>

// Problem constants
#define B_  2
#define C1_ 256
#define C2_ 256
#define K2_ 9
#define H_  64
#define W_  64
#define HW_ 4096

// ---------------------------------------------------------------------------
// Scratch (allocation-free: __device__ globals; zero-init covers pad cols)
// ---------------------------------------------------------------------------
// Main weights fp16: [step(18)=tap*2+half][o(256)][136]
__device__ __align__(128) __half g_wA[18 * 256 * 136];
// Conv weights fp16: [step(18)=kk*2+half][ocpad(32)][136]
__device__ __align__(128) __half g_wC[18 * 32 * 136];
// Packed input fp16 channel-quads: [b][c4(64)][hw] as uint2 (4 ch per elem)
__device__ __align__(128) uint2 g_xq[B_ * 64 * HW_];

// ---------------------------------------------------------------------------
// PTX helpers (plain sm_103-legal)
// ---------------------------------------------------------------------------
__device__ __forceinline__ uint32_t smem_u32(const void* p) {
    uint32_t a;
    asm("{ .reg .u64 t; cvta.to.shared.u64 t, %1; cvt.u32.u64 %0, t; }"
        : "=r"(a) : "l"(p));
    return a;
}
__device__ __forceinline__ void cp_async16(uint32_t saddr, const void* gaddr) {
    asm volatile("cp.async.cg.shared.global [%0], [%1], 16;"
                 :: "r"(saddr), "l"(gaddr) : "memory");
}
__device__ __forceinline__ void cp_commit() {
    asm volatile("cp.async.commit_group;" ::: "memory");
}
__device__ __forceinline__ void cp_wait1() {
    asm volatile("cp.async.wait_group 1;" ::: "memory");
}
__device__ __forceinline__ void cp_wait0() {
    asm volatile("cp.async.wait_group 0;" ::: "memory");
}
__device__ __forceinline__ void bar_sync(int id, int cnt) {
    asm volatile("bar.sync %0, %1;" :: "r"(id), "r"(cnt) : "memory");
}
__device__ __forceinline__ void bar_arrive(int id, int cnt) {
    asm volatile("bar.arrive %0, %1;" :: "r"(id), "r"(cnt) : "memory");
}
__device__ __forceinline__ void ldmatrix_x4(uint32_t& r0, uint32_t& r1,
                                            uint32_t& r2, uint32_t& r3,
                                            uint32_t addr) {
    asm volatile("ldmatrix.sync.aligned.m8n8.x4.shared.b16 {%0,%1,%2,%3}, [%4];"
                 : "=r"(r0), "=r"(r1), "=r"(r2), "=r"(r3) : "r"(addr));
}
__device__ __forceinline__ void mma_f16(float& d0, float& d1, float& d2, float& d3,
                                        uint32_t a0, uint32_t a1, uint32_t a2, uint32_t a3,
                                        uint32_t b0, uint32_t b1) {
    asm volatile(
        "mma.sync.aligned.m16n8k16.row.col.f32.f16.f16.f32 "
        "{%0,%1,%2,%3}, {%4,%5,%6,%7}, {%8,%9}, {%0,%1,%2,%3};"
        : "+f"(d0), "+f"(d1), "+f"(d2), "+f"(d3)
        : "r"(a0), "r"(a1), "r"(a2), "r"(a3), "r"(b0), "r"(b1));
}

// Barrier ids (as in R14)
#define BAR_META  2     // producers-only meta handoff (256)
#define BAR_OM    3     // om handoff: consumers arrive, producers sync (512)
#define BAR_FULL  4     // +buf : B buffer full (512)
#define BAR_EMPTY 6     // +buf : B buffer empty (512)
#define BAR_XT    8     // xtile ready: producers arrive, consumers sync (512)
#define BAR_WR    9     // +slot : conv weight slot ready (warp0 arrive, rest sync; 256)
#define BAR_WF    11    // +slot : conv weight slot free (rest arrive, warp0 sync; 256)

// ---------------------------------------------------------------------------
// Kernel 0: pack everything (weights fp16 + x channel-quads)
// ---------------------------------------------------------------------------
__global__ void pack_all(const float* __restrict__ w_dcn,
                         const float* __restrict__ w_off,
                         const float* __restrict__ x) {
    int idx = blockIdx.x * 256 + threadIdx.x;
    if (idx < 9 * 256 * 256) {
        int t = idx >> 16;
        int r = idx & 65535;
        int o = r >> 8;
        int c = r & 255;
        float w = w_dcn[o * (C1_ * K2_) + c * K2_ + t];
        int s = t * 2 + (c >> 7);
        int cl = c & 127;
        g_wA[(size_t)s * (256 * 136) + (size_t)o * 136 + cl] = __float2half_rn(w);
    }
    if (idx < 27 * 2304) {
        int oc = idx / 2304;
        int r  = idx % 2304;
        int c  = r / 9;
        int kk = r % 9;
        int s = kk * 2 + (c >> 7);
        int cl = c & 127;
        g_wC[(size_t)s * (32 * 136) + (size_t)oc * 136 + cl] =
            __float2half_rn(w_off[idx]);
    }
    if (idx < B_ * 64 * HW_) {
        int s  = idx & (HW_ - 1);
        int r  = idx >> 12;
        int c4 = r & 63;
        int b  = r >> 6;
        const float* xp = x + ((size_t)(b * C1_ + c4 * 4) << 12) + s;
        __half2 lo = __floats2half2_rn(xp[0],       xp[HW_]);
        __half2 hi = __floats2half2_rn(xp[2 * HW_], xp[3 * HW_]);
        uint2 v;
        v.x = *(uint32_t*)&lo;
        v.y = *(uint32_t*)&hi;
        g_xq[idx] = v;
    }
}

// ---------------------------------------------------------------------------
// Fused kernel, 512 threads: warps 0-7 consumers, 8-15 producers.
// Phase 1: implicit-im2col conv GEMM (16oc x 16px per warp) -> om smem.
// Phase 2: DCN GEMM (decoupled 2-buffer pipeline) + BN + SiLU.
// ---------------------------------------------------------------------------
#define WROW      136
#define WROWB     272
#define WSLICE_B  8704u
#define WWARP_B   17408u
#define BBASE     139264u
#define BBUF_B    17408u
#define META_O    174080u
#define SMEM_BYTES (META_O + 2048u + 8192u)
// xtile: [y(3)][ci(66)][c(264 halves)] at smem offset 0
#define XT_CI_B   528u
#define XT_Y_B    34848u

__global__ __launch_bounds__(512, 1) void dcn_fused(const float* __restrict__ b_off,
                                                    const float* __restrict__ gamma,
                                                    const float* __restrict__ beta,
                                                    const float* __restrict__ rmean,
                                                    const float* __restrict__ rvar,
                                                    float* __restrict__ out) {
    extern __shared__ __align__(128) unsigned char smem_raw[];
    const uint32_t smem_base = smem_u32(smem_raw);

    int b = blockIdx.x >> 6;
    int h = blockIdx.x & 63;
    int tid = threadIdx.x;
    int wid = tid >> 5;
    int lane = tid & 31;

    float* swt  = (float*)(smem_raw + META_O);
    int*   sidx = (int*)(smem_raw + META_O + 1024);
    float* om   = (float*)(smem_raw + META_O + 2048);   // [oc][64]
    const uint2* xqb = g_xq + ((size_t)b << 18);

    if (wid >= 8) {
        // ========================= PRODUCERS (8 warps) =========================
        int ptid = tid - 256;
        int p  = ptid & 63;
        int cg = ptid >> 6;

        // ---- phase 1: fill xtile once (3 rows, 66 cols incl. zero borders)
        for (int idx = ptid; idx < 3 * 66 * 8; idx += 256) {
            int g8 = idx & 7;
            int rr = idx >> 3;
            int ci = rr % 66;
            int y  = rr / 66;
            int gy = h - 1 + y;
            int col = ci - 1;
            unsigned char* dstp = smem_raw + (uint32_t)y * XT_Y_B +
                                  (uint32_t)ci * XT_CI_B + (uint32_t)g8 * 64u;
            if (gy >= 0 && gy < H_ && col >= 0 && col < W_) {
                int si = gy * W_ + col;
                uint2 v[8];
#pragma unroll
                for (int j = 0; j < 8; ++j)
                    v[j] = xqb[((size_t)(g8 * 8 + j) << 12) + si];
#pragma unroll
                for (int j = 0; j < 8; ++j)
                    *(uint2*)(dstp + j * 8) = v[j];
            } else {
                uint4 z = make_uint4(0u, 0u, 0u, 0u);
#pragma unroll
                for (int j = 0; j < 4; ++j)
                    *(uint4*)(dstp + j * 16) = z;
            }
        }
        bar_arrive(BAR_XT, 512);

        // wait for consumers to publish om
        bar_sync(BAR_OM, 512);

        auto make_meta = [&](int t) {
            bar_sync(BAR_META, 256);
            if (ptid < 64) {
                int w = ptid;
                float py = (float)(h - 1 + t / 3) + om[(2 * t) * 64 + w];
                float px = (float)(w - 1 + t % 3) + om[(2 * t + 1) * 64 + w];
                float m = 1.f / (1.f + __expf(-om[(18 + t) * 64 + w]));
                float y0f = floorf(py), x0f = floorf(px);
                float ly = py - y0f, lx = px - x0f;
                int y0 = (int)y0f, x0 = (int)x0f;
                int y1 = y0 + 1, x1 = x0 + 1;
                float vy0 = (y0 >= 0 && y0 < H_) ? 1.f : 0.f;
                float vy1 = (y1 >= 0 && y1 < H_) ? 1.f : 0.f;
                float vx0 = (x0 >= 0 && x0 < W_) ? 1.f : 0.f;
                float vx1 = (x1 >= 0 && x1 < W_) ? 1.f : 0.f;
                int cy0 = min(max(y0, 0), H_ - 1), cy1 = min(max(y1, 0), H_ - 1);
                int cx0 = min(max(x0, 0), W_ - 1), cx1 = min(max(x1, 0), W_ - 1);
                swt[0 * 64 + w] = (1.f - ly) * (1.f - lx) * m * vy0 * vx0;
                swt[1 * 64 + w] = (1.f - ly) * lx * m * vy0 * vx1;
                swt[2 * 64 + w] = ly * (1.f - lx) * m * vy1 * vx0;
                swt[3 * 64 + w] = ly * lx * m * vy1 * vx1;
                sidx[0 * 64 + w] = cy0 * W_ + cx0;
                sidx[1 * 64 + w] = cy0 * W_ + cx1;
                sidx[2 * 64 + w] = cy1 * W_ + cx0;
                sidx[3 * 64 + w] = cy1 * W_ + cx1;
            }
            bar_sync(BAR_META, 256);
        };

        auto make_chunk = [&](int s) {
            int q = s & 1;
            int i0 = sidx[p],       i1 = sidx[64 + p];
            int i2 = sidx[128 + p], i3 = sidx[192 + p];
            float w0 = swt[p],       w1 = swt[64 + p];
            float w2 = swt[128 + p], w3 = swt[192 + p];
            unsigned char* Bb = smem_raw + BBASE + (uint32_t)(s & 1) * BBUF_B;
            uint32_t rowoff = (uint32_t)p * WROWB;
#pragma unroll
            for (int g2 = 0; g2 < 2; ++g2) {
                uint2 t[4][4];
#pragma unroll
                for (int j = 0; j < 4; ++j) {
                    int c4 = q * 32 + cg * 8 + g2 * 4 + j;
                    const uint2* base = xqb + ((size_t)c4 << 12);
                    t[j][0] = base[i0]; t[j][1] = base[i1];
                    t[j][2] = base[i2]; t[j][3] = base[i3];
                }
#pragma unroll
                for (int j = 0; j < 4; ++j) {
                    float2 a0 = __half22float2(*(__half2*)&t[j][0].x);
                    float2 b0 = __half22float2(*(__half2*)&t[j][1].x);
                    float2 c0 = __half22float2(*(__half2*)&t[j][2].x);
                    float2 d0 = __half22float2(*(__half2*)&t[j][3].x);
                    float2 a1 = __half22float2(*(__half2*)&t[j][0].y);
                    float2 b1 = __half22float2(*(__half2*)&t[j][1].y);
                    float2 c1 = __half22float2(*(__half2*)&t[j][2].y);
                    float2 d1 = __half22float2(*(__half2*)&t[j][3].y);
                    float2 rlo, rhi;
                    rlo.x = a0.x * w0 + b0.x * w1 + c0.x * w2 + d0.x * w3;
                    rlo.y = a0.y * w0 + b0.y * w1 + c0.y * w2 + d0.y * w3;
                    rhi.x = a1.x * w0 + b1.x * w1 + c1.x * w2 + d1.x * w3;
                    rhi.y = a1.y * w0 + b1.y * w1 + c1.y * w2 + d1.y * w3;
                    __half2 hlo = __floats2half2_rn(rlo.x, rlo.y);
                    __half2 hhi = __floats2half2_rn(rhi.x, rhi.y);
                    uint2 v;
                    v.x = *(uint32_t*)&hlo;
                    v.y = *(uint32_t*)&hhi;
                    *(uint2*)(Bb + rowoff +
                              (uint32_t)(cg * 8 + g2 * 4 + j) * 8u) = v;
                }
            }
        };

        // ---- phase 2 (no leftover empty arrivals: skip waits for s<2)
        for (int s = 0; s < 18; ++s) {
            if ((s & 1) == 0) make_meta(s >> 1);
            if (s >= 2) bar_sync(BAR_EMPTY + (s & 1), 512);
            make_chunk(s);
            bar_arrive(BAR_FULL + (s & 1), 512);
        }
    } else {
        // ========================= CONSUMERS (8 warps) =========================
        int a_row = lane & 15;
        int a_cad = (lane >= 16) ? 8 : 0;
        int b_row = (lane & 7) + ((lane >= 16) ? 8 : 0);
        int b_cad = ((lane >> 3) & 1) * 8;
        int g4 = lane >> 2;
        int t4 = lane & 3;

        uint32_t wdst0 = smem_base + (uint32_t)wid * WWARP_B;

        // ---- phase 1: implicit-im2col conv MMA, warp = 16 oc x 16 px
        {
            int ochalf = wid >> 2;      // 0/1 -> oc [0,16) / [16,32)
            int pq     = wid & 3;       // px quarter: [16*pq, 16*pq+16)

            float accC[2][4];           // nt = 0,1 (two 8-px n-tiles)
#pragma unroll
            for (int nt = 0; nt < 2; nt++)
#pragma unroll
                for (int j = 0; j < 4; j++) accC[nt][j] = 0.f;

            const uint32_t slot_base = smem_base + BBASE;

            // warp 0 pre-stages conv weight taps 0 and 1 into the two slots
            if (wid == 0) {
#pragma unroll
                for (int t0 = 0; t0 < 2; ++t0) {
                    const unsigned char* src =
                        (const unsigned char*)g_wC + (size_t)t0 * 17408u;
                    uint32_t dst = slot_base + (uint32_t)t0 * 17408u;
#pragma unroll
                    for (int j = 0; j < 34; ++j) {       // 34*32*16B = 17408B
                        uint32_t off = (uint32_t)(lane + j * 32) * 16u;
                        cp_async16(dst + off, src + off);
                    }
                    cp_commit();
                }
                cp_wait1();                              // tap0 complete
                bar_arrive(BAR_WR + 0, 256);
            }

            bar_sync(BAR_XT, 512);                       // xtile ready

            for (int t = 0; t < 9; ++t) {
                int slot = t & 1;
                if (wid != 0) bar_sync(BAR_WR + slot, 256);
                uint32_t wslot = slot_base + (uint32_t)slot * 17408u;
                int ky = t / 3, kx = t % 3;
                int ci = pq * 16 + b_row + kx;           // ci = pixel + kx
                uint32_t brow = smem_base + (uint32_t)ky * XT_Y_B +
                                (uint32_t)ci * XT_CI_B;

#pragma unroll
                for (int chunk = 0; chunk < 2; ++chunk) {
#pragma unroll
                    for (int ks = 0; ks < 8; ++ks) {
                        uint32_t addrB = brow +
                            (uint32_t)(chunk * 128 + ks * 16 + b_cad) * 2;
                        uint32_t B0, B1, B2, B3;
                        ldmatrix_x4(B0, B1, B2, B3, addrB);
                        uint32_t aaddr = wslot + (uint32_t)chunk * 8704u +
                            (uint32_t)((ochalf * 16 + a_row) * WROW +
                                       ks * 16 + a_cad) * 2;
                        uint32_t A0, A1, A2, A3;
                        ldmatrix_x4(A0, A1, A2, A3, aaddr);
                        mma_f16(accC[0][0], accC[0][1], accC[0][2], accC[0][3],
                                A0, A1, A2, A3, B0, B1);
                        mma_f16(accC[1][0], accC[1][1], accC[1][2], accC[1][3],
                                A0, A1, A2, A3, B2, B3);
                    }
                }

                if (wid == 0) {
                    if (t + 2 <= 8) {
                        bar_sync(BAR_WF + slot, 256);    // slot free
                        const unsigned char* src =
                            (const unsigned char*)g_wC + (size_t)(t + 2) * 17408u;
                        uint32_t dst = slot_base + (uint32_t)slot * 17408u;
#pragma unroll
                        for (int j = 0; j < 34; ++j) {
                            uint32_t off = (uint32_t)(lane + j * 32) * 16u;
                            cp_async16(dst + off, src + off);
                        }
                        cp_commit();
                    }
                    if (t + 1 <= 8) {
                        if (t + 2 <= 8) cp_wait1(); else cp_wait0();
                        bar_arrive(BAR_WR + ((t + 1) & 1), 256);
                    }
                } else {
                    if (t + 2 <= 8) bar_arrive(BAR_WF + slot, 256);
                }
            }

            // conv epilogue -> om smem (+ bias)
            int oc_lo = ochalf * 16 + g4;
            int oc_hi = oc_lo + 8;
#pragma unroll
            for (int nt = 0; nt < 2; ++nt) {
                int col = pq * 16 + nt * 8 + t4 * 2;
                if (oc_lo < 27) {
                    float bo = b_off[oc_lo];
                    om[oc_lo * 64 + col]     = accC[nt][0] + bo;
                    om[oc_lo * 64 + col + 1] = accC[nt][1] + bo;
                }
                if (oc_hi < 27) {
                    float bo = b_off[oc_hi];
                    om[oc_hi * 64 + col]     = accC[nt][2] + bo;
                    om[oc_hi * 64 + col + 1] = accC[nt][3] + bo;
                }
            }
            bar_arrive(BAR_OM, 512);     // om published
        }

        // ---- phase 2: main DCN MMA (fp16; warp owns o in [32w, 32w+32))
        int o0 = wid * 32;
        float acc[2][8][4];
#pragma unroll
        for (int mt = 0; mt < 2; mt++)
#pragma unroll
            for (int nt = 0; nt < 8; nt++)
#pragma unroll
                for (int j = 0; j < 4; j++) acc[mt][nt][j] = 0.f;

        const unsigned char* wsrc0 = (const unsigned char*)g_wA +
                                     (size_t)wid * 8704u;

        auto cpW = [&](int s) {
            const unsigned char* src = wsrc0 + (size_t)s * 69632u;
            uint32_t dst = wdst0 + (uint32_t)(s & 1) * WSLICE_B;
#pragma unroll
            for (int j = 0; j < 17; ++j) {
                uint32_t off = (uint32_t)(lane + j * 32) * 16u;
                cp_async16(dst + off, src + off);
            }
            cp_commit();
        };

        cpW(0);

        for (int s = 0; s < 18; ++s) {
            if (s < 17) { cpW(s + 1); cp_wait1(); }
            else        { cp_wait0(); }
            bar_sync(BAR_FULL + (s & 1), 512);

            uint32_t wreg = wdst0 + (uint32_t)(s & 1) * WSLICE_B;
            uint32_t breg = smem_base + BBASE + (uint32_t)(s & 1) * BBUF_B;

#pragma unroll
            for (int ks = 0; ks < 8; ++ks) {
                uint32_t A[2][4];
#pragma unroll
                for (int mt = 0; mt < 2; ++mt) {
                    uint32_t aaddr = wreg +
                        (uint32_t)((mt * 16 + a_row) * WROW + ks * 16 + a_cad) * 2;
                    ldmatrix_x4(A[mt][0], A[mt][1], A[mt][2], A[mt][3], aaddr);
                }
                uint32_t Bf[16];
#pragma unroll
                for (int pr = 0; pr < 4; ++pr) {
                    uint32_t addr = breg +
                        (uint32_t)((pr * 16 + b_row) * WROW + ks * 16 + b_cad) * 2;
                    ldmatrix_x4(Bf[pr * 4 + 0], Bf[pr * 4 + 1],
                                Bf[pr * 4 + 2], Bf[pr * 4 + 3], addr);
                }
#pragma unroll
                for (int mt = 0; mt < 2; ++mt) {
#pragma unroll
                    for (int nt = 0; nt < 8; ++nt) {
                        float* d = acc[mt][nt];
                        mma_f16(d[0], d[1], d[2], d[3],
                                A[mt][0], A[mt][1], A[mt][2], A[mt][3],
                                Bf[nt * 2], Bf[nt * 2 + 1]);
                    }
                }
            }
            bar_arrive(BAR_EMPTY + (s & 1), 512);
        }

        // ---- epilogue: BN + SiLU
#pragma unroll
        for (int mt = 0; mt < 2; ++mt) {
            int o_lo = o0 + mt * 16 + g4;
            int o_hi = o_lo + 8;
            float invl = gamma[o_lo] * rsqrtf(rvar[o_lo] + 1e-5f);
            float bbl  = beta[o_lo] - rmean[o_lo] * invl;
            float invh = gamma[o_hi] * rsqrtf(rvar[o_hi] + 1e-5f);
            float bbh  = beta[o_hi] - rmean[o_hi] * invh;
            float* opl = out + (((size_t)b * C2_ + o_lo) * H_ + h) * W_;
            float* oph = out + (((size_t)b * C2_ + o_hi) * H_ + h) * W_;
#pragma unroll
            for (int nt = 0; nt < 8; ++nt) {
                int pp = nt * 8 + t4 * 2;
                float y0v = acc[mt][nt][0] * invl + bbl;
                float y1v = acc[mt][nt][1] * invl + bbl;
                float y2v = acc[mt][nt][2] * invh + bbh;
                float y3v = acc[mt][nt][3] * invh + bbh;
                float2 vlo, vhi;
                vlo.x = y0v / (1.f + __expf(-y0v));
                vlo.y = y1v / (1.f + __expf(-y1v));
                vhi.x = y2v / (1.f + __expf(-y2v));
                vhi.y = y3v / (1.f + __expf(-y3v));
                *(float2*)(opl + pp) = vlo;
                *(float2*)(oph + pp) = vhi;
            }
        }
    }
}

// ---------------------------------------------------------------------------
extern "C" void kernel_launch(void* const* d_in, const int* in_sizes, int n_in,
                              void* d_out, int out_size) {
    const float* x      = (const float*)d_in[0];
    const float* w_off  = (const float*)d_in[1];
    const float* b_off  = (const float*)d_in[2];
    const float* w_dcn  = (const float*)d_in[3];
    const float* gamma  = (const float*)d_in[4];
    const float* beta   = (const float*)d_in[5];
    const float* rmean  = (const float*)d_in[6];
    const float* rvar   = (const float*)d_in[7];
    float* out = (float*)d_out;

    cudaFuncSetAttribute(dcn_fused, cudaFuncAttributeMaxDynamicSharedMemorySize,
                         SMEM_BYTES);

    pack_all<<<2304, 256>>>(w_dcn, w_off, x);
    dcn_fused<<<B_ * H_, 512, SMEM_BYTES>>>(b_off, gamma, beta, rmean, rvar, out);
}